// round 14
// baseline (speedup 1.0000x reference)
#include <cuda_runtime.h>
#include <cuda_fp16.h>
#include <cstdint>
#include <math.h>

// ---------------------------------------------------------------------------
// SwinBlock on sm_103a — fp16 HMMA GEMMs (BN=192 high-intensity tiles)
// + HMMA windowed attention.
// B=16, H=W=56, C=192, heads=6 (hd=32), WS=7, SHIFT=3, HIDDEN=1152
// ---------------------------------------------------------------------------

#define WSZ    7
#define SHIFT  3
#define HEADS  6
#define DIM    192
#define HIDDEN 1152
#define EPS    1e-5f
#define IMG    56
#define NTOK   49
#define MAXM   50176   // 16*56*56

typedef __half f16;

// ------------------------- scratch (static device) -------------------------
__device__ f16   g_qkv [(size_t)MAXM * 3 * DIM];
__device__ float g_x2  [(size_t)MAXM * DIM];
__device__ f16   g_h   [(size_t)MAXM * DIM];
__device__ f16   g_at  [(size_t)MAXM * DIM];
__device__ f16   g_hid [(size_t)MAXM * HIDDEN];
__device__ f16   g_wq[576 * DIM];
__device__ f16   g_wp[DIM * DIM];
__device__ f16   g_w1[HIDDEN * DIM];
__device__ f16   g_w2[DIM * HIDDEN];

__device__ __forceinline__ int win_to_orig(int r) {
    int w   = r / NTOK;
    int n   = r - w * NTOK;
    int b   = w >> 6;
    int win = w & 63;
    int hs  = (win >> 3) * WSZ + n / WSZ;
    int ws  = (win & 7)  * WSZ + n % WSZ;
    int h   = hs + SHIFT; if (h >= IMG) h -= IMG;
    int x   = ws + SHIFT; if (x >= IMG) x -= IMG;
    return b * (IMG * IMG) + h * IMG + x;
}

// ------------------------- fused weight conversion --------------------------
#define NQ (576 * DIM)
#define NP (DIM * DIM)
#define N1 (HIDDEN * DIM)
#define N2 (DIM * HIDDEN)
__global__ void conv4_kernel(const float* __restrict__ wq_f, f16* __restrict__ wq,
                             const float* __restrict__ wp_f, f16* __restrict__ wp,
                             const float* __restrict__ w1_f, f16* __restrict__ w1,
                             const float* __restrict__ w2_f, f16* __restrict__ w2) {
    int i = blockIdx.x * blockDim.x + threadIdx.x;
    int total = NQ + NP + N1 + N2;
    if (i >= total) return;
    if (i < NQ)                { wq[i] = __float2half_rn(wq_f[i]); return; }
    i -= NQ;
    if (i < NP)                { wp[i] = __float2half_rn(wp_f[i]); return; }
    i -= NP;
    if (i < N1)                { w1[i] = __float2half_rn(w1_f[i]); return; }
    i -= N1;
    w2[i] = __float2half_rn(w2_f[i]);
}

// ------------------------- LayerNorm (fp16 out) -----------------------------
__global__ void ln_kernel(const float* __restrict__ in, f16* __restrict__ out,
                          const float* __restrict__ gam, const float* __restrict__ bet,
                          int M, int remap) {
    int r = blockIdx.x * (blockDim.x >> 5) + (threadIdx.x >> 5);
    if (r >= M) return;
    int lane = threadIdx.x & 31;
    int src  = remap ? win_to_orig(r) : r;
    const float* row = in + (size_t)src * DIM;

    float v[6], s = 0.f;
#pragma unroll
    for (int j = 0; j < 6; j++) { v[j] = row[lane + 32 * j]; s += v[j]; }
#pragma unroll
    for (int o = 16; o; o >>= 1) s += __shfl_xor_sync(0xFFFFFFFFu, s, o);
    float mean = s * (1.f / DIM);
    float vs = 0.f;
#pragma unroll
    for (int j = 0; j < 6; j++) { float d = v[j] - mean; vs += d * d; }
#pragma unroll
    for (int o = 16; o; o >>= 1) vs += __shfl_xor_sync(0xFFFFFFFFu, vs, o);
    float rstd = rsqrtf(vs * (1.f / DIM) + EPS);

    size_t ro = (size_t)r * DIM;
#pragma unroll
    for (int j = 0; j < 6; j++) {
        int c = lane + 32 * j;
        out[ro + c] = __float2half_rn((v[j] - mean) * rstd * gam[c] + bet[c]);
    }
}

// ------------------------- mma.sync helpers --------------------------------
__device__ __forceinline__ void ldsm4(uint32_t r[4], const f16* p) {
    uint32_t a = (uint32_t)__cvta_generic_to_shared(p);
    asm volatile("ldmatrix.sync.aligned.m8n8.x4.shared.b16 {%0,%1,%2,%3}, [%4];"
                 : "=r"(r[0]), "=r"(r[1]), "=r"(r[2]), "=r"(r[3]) : "r"(a));
}
__device__ __forceinline__ void mma16816(float c[4], const uint32_t a[4],
                                         uint32_t b0, uint32_t b1) {
    asm volatile(
        "mma.sync.aligned.m16n8k16.row.col.f32.f16.f16.f32 "
        "{%0,%1,%2,%3}, {%4,%5,%6,%7}, {%8,%9}, {%0,%1,%2,%3};"
        : "+f"(c[0]), "+f"(c[1]), "+f"(c[2]), "+f"(c[3])
        : "r"(a[0]), "r"(a[1]), "r"(a[2]), "r"(a[3]), "r"(b0), "r"(b1));
}
__device__ __forceinline__ void cp16(f16* dst, const f16* src) {
    uint32_t d = (uint32_t)__cvta_generic_to_shared(dst);
    asm volatile("cp.async.cg.shared.global [%0], [%1], 16;" :: "r"(d), "l"(src));
}
__device__ __forceinline__ void cp_commit() {
    asm volatile("cp.async.commit_group;" ::: "memory");
}
template <int N>
__device__ __forceinline__ void cp_wait() {
    asm volatile("cp.async.wait_group %0;" :: "n"(N) : "memory");
}
__device__ __forceinline__ uint32_t h2u(float a, float b) {
    __half2 t = __floats2half2_rn(a, b);
    return *(uint32_t*)&t;
}

// ---------------------------------------------------------------------------
// GEMM: C = A(f16) @ W^T(f16) + bias. BM=128, BN=192, BK=32.
// 256 threads, 8 warps as 4M x 2N -> warp tile 32x96 (acc[2][12][4]).
// 3-stage cp.async pipeline.
// MODE 0 f16, 1 remap+res fp32, 2 GELU f16, 3 res fp32.
// ---------------------------------------------------------------------------
#define SKP 40
#define ST_A  0
#define ST_W  (128 * SKP)
#define STAGE_ELEMS (320 * SKP)              // (128 A + 192 W) rows
#define GSMEM_BYTES (3 * STAGE_ELEMS * 2)    // 76800 B

template <int MODE>
__global__ void __launch_bounds__(256)
gemm_tc(const f16* __restrict__ A, const f16* __restrict__ W,
        const float* __restrict__ bias, int N, int K,
        float* __restrict__ Cf, f16* __restrict__ Ch,
        const float* __restrict__ res) {
    extern __shared__ f16 sm[];
    const int m0 = blockIdx.y * 128, n0 = blockIdx.x * 192;
    const int tid = threadIdx.x, lane = tid & 31, w = tid >> 5;
    const int wm = w & 3, wn = w >> 2;
    const int NC = K / 32;

    auto load_stage = [&](int c) {
        f16* buf = sm + (c % 3) * STAGE_ELEMS;
        const int k0 = c * 32;
#pragma unroll
        for (int it = 0; it < 2; it++) {          // A: 512 16B chunks
            int i = tid + it * 256;
            int row = i >> 2, q = i & 3;
            cp16(buf + ST_A + row * SKP + q * 8,
                 A + (size_t)(m0 + row) * K + k0 + q * 8);
        }
#pragma unroll
        for (int it = 0; it < 3; it++) {          // W: 768 16B chunks (192 rows)
            int i = tid + it * 256;
            int row = i >> 2, q = i & 3;
            cp16(buf + ST_W + row * SKP + q * 8,
                 W + (size_t)(n0 + row) * K + k0 + q * 8);
        }
        cp_commit();
    };

    float acc[2][12][4] = {};

    load_stage(0);
    load_stage(1);

    for (int c = 0; c < NC; c++) {
        if (c + 1 < NC) cp_wait<1>(); else cp_wait<0>();
        __syncthreads();
        if (c + 2 < NC) load_stage(c + 2);

        f16* buf = sm + (c % 3) * STAGE_ELEMS;
        const int lrow = lane & 15;
#pragma unroll
        for (int kk = 0; kk < 2; kk++) {
            const int lcol = kk * 16 + (lane >> 4) * 8;
            uint32_t a[2][4];
#pragma unroll
            for (int mi = 0; mi < 2; mi++)
                ldsm4(a[mi], buf + ST_A + (wm * 32 + mi * 16 + lrow) * SKP + lcol);
#pragma unroll
            for (int nj = 0; nj < 6; nj++) {
                uint32_t wr[4];
                ldsm4(wr, buf + ST_W + (wn * 96 + nj * 16 + lrow) * SKP + lcol);
#pragma unroll
                for (int mi = 0; mi < 2; mi++)
#pragma unroll
                    for (int j = 0; j < 2; j++)
                        mma16816(acc[mi][nj * 2 + j], a[mi], wr[j], wr[2 + j]);
            }
        }
        __syncthreads();
    }

    // ---------------- epilogue ----------------
    const int g = lane >> 2, t4 = lane & 3;
#pragma unroll
    for (int mi = 0; mi < 2; mi++) {
#pragma unroll
        for (int half = 0; half < 2; half++) {
            int r = m0 + wm * 32 + mi * 16 + g + half * 8;
            int ro = (MODE == 1) ? win_to_orig(r) : r;
#pragma unroll
            for (int ni = 0; ni < 12; ni++) {
                int cc = n0 + wn * 96 + ni * 8 + t4 * 2;
                float v0 = acc[mi][ni][half * 2 + 0] + bias[cc];
                float v1 = acc[mi][ni][half * 2 + 1] + bias[cc + 1];
                if (MODE == 0) {
                    *(__half2*)&Ch[(size_t)r * N + cc] = __floats2half2_rn(v0, v1);
                } else if (MODE == 1) {
                    size_t o = (size_t)ro * DIM + cc;
                    Cf[o]     = v0 + res[o];
                    Cf[o + 1] = v1 + res[o + 1];
                } else if (MODE == 2) {
                    v0 = 0.5f * v0 * (1.0f + erff(v0 * 0.70710678118654752f));
                    v1 = 0.5f * v1 * (1.0f + erff(v1 * 0.70710678118654752f));
                    *(__half2*)&Ch[(size_t)r * N + cc] = __floats2half2_rn(v0, v1);
                } else {
                    size_t o = (size_t)r * DIM + cc;
                    Cf[o]     = v0 + res[o];
                    Cf[o + 1] = v1 + res[o + 1];
                }
            }
        }
    }
}

// ---------------------------------------------------------------------------
// HMMA windowed attention (unchanged from R13 passing kernel).
// 4 (window,head) pairs per 256-thread block; 2 warps per pair.
// ---------------------------------------------------------------------------
#define AQ_ELEMS (64 * 40)
#define AK_ELEMS (64 * 40)
#define AV_ELEMS (32 * 72)
#define PAIR_HALVES (AQ_ELEMS + AK_ELEMS + AV_ELEMS)   // 7424
#define PAIR_BYTES  (PAIR_HALVES * 2 + 704)            // 15552
#define ATT_SMEM    (4 * PAIR_BYTES)                   // 62208

__global__ void __launch_bounds__(256)
attn_mma(const f16* __restrict__ qkv, const float* __restrict__ rpb,
         f16* __restrict__ oat) {
    extern __shared__ char asmem[];
    const int tid  = threadIdx.x;
    const int warp = tid >> 5, lane = tid & 31;
    const int p    = warp >> 1, wp = warp & 1;
    const int pair = blockIdx.x * 4 + p;
    const int w    = pair / HEADS, h = pair % HEADS;

    f16*   q   = (f16*)(asmem + p * PAIR_BYTES);
    f16*   k   = q + AQ_ELEMS;
    f16*   vT  = k + AK_ELEMS;
    float* bsh = (float*)(vT + AV_ELEMS);
    const int t64 = tid & 63;

    for (int i = t64; i < PAIR_HALVES / 8; i += 64)
        ((uint4*)q)[i] = make_uint4(0, 0, 0, 0);
    __syncthreads();

    const f16* qg = qkv + (size_t)(w * NTOK) * (3 * DIM) + h * 32;
    for (int i = t64; i < NTOK * 16; i += 64) {
        int t = i >> 4, d2 = (i & 15) * 2;
        const f16* src = qg + (size_t)t * (3 * DIM) + d2;
        *(__half2*)(q + t * 40 + d2) = *(const __half2*)(src);
        *(__half2*)(k + t * 40 + d2) = *(const __half2*)(src + DIM);
        __half2 vv = *(const __half2*)(src + 2 * DIM);
        vT[d2 * 72 + t]       = __low2half(vv);
        vT[(d2 + 1) * 72 + t] = __high2half(vv);
    }
    for (int i = t64; i < 169; i += 64) bsh[i] = rpb[i * HEADS + h];
    __syncthreads();

    const int lrow = lane & 15;
    const int lhi8 = (lane >> 4) * 8;
    const int g = lane >> 2, t4 = lane & 3;

    float acc[2][8][4] = {};
#pragma unroll
    for (int kk = 0; kk < 2; kk++) {
        const int lcol = kk * 16 + lhi8;
        uint32_t a[2][4];
#pragma unroll
        for (int mi = 0; mi < 2; mi++)
            ldsm4(a[mi], q + (wp * 32 + mi * 16 + lrow) * 40 + lcol);
#pragma unroll
        for (int nj4 = 0; nj4 < 4; nj4++) {
            uint32_t wr[4];
            ldsm4(wr, k + (nj4 * 16 + lrow) * 40 + lcol);
#pragma unroll
            for (int mi = 0; mi < 2; mi++)
#pragma unroll
                for (int j = 0; j < 2; j++)
                    mma16816(acc[mi][nj4 * 2 + j], a[mi], wr[j], wr[2 + j]);
        }
    }

    const float scale = 0.17677669529663687f;
    float mx[2][2], sums[2][2];
    int rq7[2][2], rm7[2][2], rr[2][2];
#pragma unroll
    for (int mi = 0; mi < 2; mi++)
#pragma unroll
        for (int hf = 0; hf < 2; hf++) {
            int r = wp * 32 + mi * 16 + g + 8 * hf;
            rr[mi][hf] = r;
            int rd = (r * 37) >> 8;
            rq7[mi][hf] = rd; rm7[mi][hf] = r - 7 * rd;
            mx[mi][hf] = -1e30f; sums[mi][hf] = 0.f;
        }
#pragma unroll
    for (int mi = 0; mi < 2; mi++)
#pragma unroll
        for (int nj = 0; nj < 8; nj++)
#pragma unroll
            for (int cj = 0; cj < 4; cj++) {
                int hf = cj >> 1;
                int c  = nj * 8 + 2 * t4 + (cj & 1);
                float s;
                if (c < NTOK && rr[mi][hf] < NTOK) {
                    int cd = (c * 37) >> 8, cm = c - 7 * cd;
                    int idx = (rq7[mi][hf] - cd + 6) * 13 + (rm7[mi][hf] - cm + 6);
                    s = acc[mi][nj][cj] * scale + bsh[idx];
                } else s = -1e30f;
                acc[mi][nj][cj] = s;
                mx[mi][hf] = fmaxf(mx[mi][hf], s);
            }
#pragma unroll
    for (int mi = 0; mi < 2; mi++)
#pragma unroll
        for (int hf = 0; hf < 2; hf++) {
            float m = mx[mi][hf];
            m = fmaxf(m, __shfl_xor_sync(0xFFFFFFFFu, m, 1));
            m = fmaxf(m, __shfl_xor_sync(0xFFFFFFFFu, m, 2));
            mx[mi][hf] = m;
        }
#pragma unroll
    for (int mi = 0; mi < 2; mi++)
#pragma unroll
        for (int nj = 0; nj < 8; nj++)
#pragma unroll
            for (int cj = 0; cj < 4; cj++) {
                int hf = cj >> 1;
                float e = __expf(acc[mi][nj][cj] - mx[mi][hf]);
                acc[mi][nj][cj] = e;
                sums[mi][hf] += e;
            }
#pragma unroll
    for (int mi = 0; mi < 2; mi++)
#pragma unroll
        for (int hf = 0; hf < 2; hf++) {
            float s = sums[mi][hf];
            s += __shfl_xor_sync(0xFFFFFFFFu, s, 1);
            s += __shfl_xor_sync(0xFFFFFFFFu, s, 2);
            sums[mi][hf] = s;
        }

    uint32_t pa[2][4][4];
#pragma unroll
    for (int mi = 0; mi < 2; mi++)
#pragma unroll
        for (int kt = 0; kt < 4; kt++) {
            pa[mi][kt][0] = h2u(acc[mi][2 * kt][0],     acc[mi][2 * kt][1]);
            pa[mi][kt][1] = h2u(acc[mi][2 * kt][2],     acc[mi][2 * kt][3]);
            pa[mi][kt][2] = h2u(acc[mi][2 * kt + 1][0], acc[mi][2 * kt + 1][1]);
            pa[mi][kt][3] = h2u(acc[mi][2 * kt + 1][2], acc[mi][2 * kt + 1][3]);
        }

    float o[2][4][4] = {};
#pragma unroll
    for (int kt = 0; kt < 4; kt++) {
        const int kc = kt * 16 + lhi8;
#pragma unroll
        for (int nv = 0; nv < 2; nv++) {
            uint32_t wr[4];
            ldsm4(wr, vT + (nv * 16 + lrow) * 72 + kc);
#pragma unroll
            for (int mi = 0; mi < 2; mi++)
#pragma unroll
                for (int j = 0; j < 2; j++)
                    mma16816(o[mi][nv * 2 + j], pa[mi][kt], wr[j], wr[2 + j]);
        }
    }

#pragma unroll
    for (int mi = 0; mi < 2; mi++)
#pragma unroll
        for (int hf = 0; hf < 2; hf++) {
            int r = rr[mi][hf];
            if (r < NTOK) {
                float inv = 1.f / sums[mi][hf];
                f16* orow = oat + (size_t)(w * NTOK + r) * DIM + h * 32;
#pragma unroll
                for (int nd = 0; nd < 4; nd++) {
                    int d0 = nd * 8 + 2 * t4;
                    *(__half2*)(orow + d0) = __floats2half2_rn(
                        o[mi][nd][hf * 2 + 0] * inv, o[mi][nd][hf * 2 + 1] * inv);
                }
            }
        }
}

// ---------------------------------------------------------------------------
extern "C" void kernel_launch(void* const* d_in, const int* in_sizes, int n_in,
                              void* d_out, int out_size) {
    const float* x = (const float*)d_in[0];
    int base = n_in - 13;
    const float* ln1_g  = (const float*)d_in[base + 0];
    const float* ln1_b  = (const float*)d_in[base + 1];
    const float* qkv_w  = (const float*)d_in[base + 2];
    const float* qkv_b  = (const float*)d_in[base + 3];
    const float* rpb    = (const float*)d_in[base + 4];
    const float* proj_w = (const float*)d_in[base + 5];
    const float* proj_b = (const float*)d_in[base + 6];
    const float* ln2_g  = (const float*)d_in[base + 7];
    const float* ln2_b  = (const float*)d_in[base + 8];
    const float* fc1_w  = (const float*)d_in[base + 9];
    const float* fc1_b  = (const float*)d_in[base + 10];
    const float* fc2_w  = (const float*)d_in[base + 11];
    const float* fc2_b  = (const float*)d_in[base + 12];

    const int Bsz = in_sizes[0] / (IMG * IMG * DIM);
    const int M   = Bsz * IMG * IMG;

    float *x2;
    f16 *qkv, *h, *at, *hid, *wq, *wp, *w1, *w2;
    cudaGetSymbolAddress((void**)&qkv, g_qkv);
    cudaGetSymbolAddress((void**)&x2,  g_x2);
    cudaGetSymbolAddress((void**)&h,   g_h);
    cudaGetSymbolAddress((void**)&at,  g_at);
    cudaGetSymbolAddress((void**)&hid, g_hid);
    cudaGetSymbolAddress((void**)&wq,  g_wq);
    cudaGetSymbolAddress((void**)&wp,  g_wp);
    cudaGetSymbolAddress((void**)&w1,  g_w1);
    cudaGetSymbolAddress((void**)&w2,  g_w2);

    cudaFuncSetAttribute(gemm_tc<0>, cudaFuncAttributeMaxDynamicSharedMemorySize, GSMEM_BYTES);
    cudaFuncSetAttribute(gemm_tc<1>, cudaFuncAttributeMaxDynamicSharedMemorySize, GSMEM_BYTES);
    cudaFuncSetAttribute(gemm_tc<2>, cudaFuncAttributeMaxDynamicSharedMemorySize, GSMEM_BYTES);
    cudaFuncSetAttribute(gemm_tc<3>, cudaFuncAttributeMaxDynamicSharedMemorySize, GSMEM_BYTES);
    cudaFuncSetAttribute(attn_mma,   cudaFuncAttributeMaxDynamicSharedMemorySize, ATT_SMEM);

    const int lnGrid = (M + 7) / 8;
    const int mT = M / 128;                   // 392
    const int nPairs = (M / NTOK) * HEADS;    // 6144

    {
        int total = NQ + NP + N1 + N2;
        conv4_kernel<<<(total + 255) / 256, 256>>>(qkv_w, wq, proj_w, wp,
                                                   fc1_w, w1, fc2_w, w2);
    }

    // 1. LN1 fused shift + window partition -> f16
    ln_kernel<<<lnGrid, 256>>>(x, h, ln1_g, ln1_b, M, 1);
    // 2. QKV GEMM -> f16
    gemm_tc<0><<<dim3(576 / 192, mT), 256, GSMEM_BYTES>>>(
        h, wq, qkv_b, 576, DIM, nullptr, qkv, nullptr);
    // 3. HMMA attention -> f16 (window layout)
    attn_mma<<<nPairs / 4, 256, ATT_SMEM>>>(qkv, rpb, at);
    // 4. proj GEMM + window-reverse + residual -> x2 (fp32)
    gemm_tc<1><<<dim3(DIM / 192, mT), 256, GSMEM_BYTES>>>(
        at, wp, proj_b, DIM, DIM, x2, nullptr, x);
    // 5. LN2 -> f16
    ln_kernel<<<lnGrid, 256>>>(x2, h, ln2_g, ln2_b, M, 0);
    // 6. fc1 GEMM + GELU -> f16
    gemm_tc<2><<<dim3(HIDDEN / 192, mT), 256, GSMEM_BYTES>>>(
        h, w1, fc1_b, HIDDEN, DIM, nullptr, hid, nullptr);
    // 7. fc2 GEMM + residual -> d_out (fp32)
    gemm_tc<3><<<dim3(DIM / 192, mT), 256, GSMEM_BYTES>>>(
        hid, w2, fc2_b, DIM, HIDDEN, (float*)d_out, nullptr, x2);
}